// round 1
// baseline (speedup 1.0000x reference)
#include <cuda_runtime.h>

// AdditiveAttention: out[b,i,:] = softmax_j( sum_h tanh(qp[b,i,h]+kp[b,j,h])*wv[h], mask j<vl[b] ) @ values[b]
// B=8, LQ=128, LK=1024, D=512, H=256, DV=512

#define NEG_FILL (-1000000.0f)

static constexpr int B_  = 8;
static constexpr int LQ_ = 128;
static constexpr int LK_ = 1024;
static constexpr int D_  = 512;
static constexpr int H_  = 256;
static constexpr int DV_ = 512;
static constexpr int QT  = 8;     // queries per CTA
static constexpr int NTH = 512;   // threads per CTA (16 warps)

__device__ float g_qproj[B_ * LQ_ * H_];   // [1024, 256]
__device__ float g_kproj[B_ * LK_ * H_];   // [8192, 256]

__device__ __forceinline__ float tanh_fast(float x) {
    float y;
    asm("tanh.approx.f32 %0, %1;" : "=f"(y) : "f"(x));
    return y;
}

// C[M, 256] = A[M, 512] @ W[512, 256]; which=0 -> g_qproj, which=1 -> g_kproj
__global__ void proj_kernel(const float* __restrict__ A, const float* __restrict__ W,
                            int which) {
    __shared__ float As[32][33];
    __shared__ float Ws[32][33];
    float* C = which ? g_kproj : g_qproj;
    const int tx = threadIdx.x, ty = threadIdx.y;
    const int m0 = blockIdx.y * 32, n0 = blockIdx.x * 32;
    float acc = 0.f;
    for (int k0 = 0; k0 < D_; k0 += 32) {
        As[ty][tx] = A[(size_t)(m0 + ty) * D_ + k0 + tx];
        Ws[ty][tx] = W[(size_t)(k0 + ty) * H_ + n0 + tx];
        __syncthreads();
#pragma unroll
        for (int kk = 0; kk < 32; kk++) acc += As[ty][kk] * Ws[kk][tx];
        __syncthreads();
    }
    C[(size_t)(m0 + ty) * H_ + n0 + tx] = acc;
}

__global__ __launch_bounds__(NTH, 1) void fused_attn(
    const float* __restrict__ values,
    const float* __restrict__ wv,
    const int* __restrict__ valid_lens,
    float* __restrict__ out) {
    __shared__ float s_sc[QT][LK_];   // scores, then exp() weights (32 KB)
    __shared__ float s_inv[QT];

    const int b  = blockIdx.x >> 4;            // LQ_/QT = 16 CTAs per batch
    const int q0 = (blockIdx.x & 15) * QT;
    const int tid = threadIdx.x, warp = tid >> 5, lane = tid & 31;

    // lane l covers h in {4l..4l+3} and {128+4l..128+4l+3}
    const float4* wv4 = (const float4*)wv;
    const float4 w0 = wv4[lane];
    const float4 w1 = wv4[32 + lane];
    float4 qr0[QT], qr1[QT];
#pragma unroll
    for (int q = 0; q < QT; q++) {
        const float4* qp = (const float4*)(g_qproj + (size_t)(b * LQ_ + q0 + q) * H_);
        qr0[q] = qp[lane];
        qr1[q] = qp[32 + lane];
    }

    // ---- Phase 1: scores[q][j] = sum_h tanh(q+k)*wv ----
    const float4* kb = (const float4*)(g_kproj + (size_t)b * LK_ * H_);
    for (int j = warp; j < LK_; j += 16) {
        const float4 k0 = kb[(size_t)j * 64 + lane];
        const float4 k1 = kb[(size_t)j * 64 + 32 + lane];
        float acc[QT];
#pragma unroll
        for (int q = 0; q < QT; q++) {
            float a;
            a  = tanh_fast(qr0[q].x + k0.x) * w0.x;
            a += tanh_fast(qr0[q].y + k0.y) * w0.y;
            a += tanh_fast(qr0[q].z + k0.z) * w0.z;
            a += tanh_fast(qr0[q].w + k0.w) * w0.w;
            a += tanh_fast(qr1[q].x + k1.x) * w1.x;
            a += tanh_fast(qr1[q].y + k1.y) * w1.y;
            a += tanh_fast(qr1[q].z + k1.z) * w1.z;
            a += tanh_fast(qr1[q].w + k1.w) * w1.w;
            acc[q] = a;
        }
#pragma unroll
        for (int off = 16; off; off >>= 1) {
#pragma unroll
            for (int q = 0; q < QT; q++)
                acc[q] += __shfl_xor_sync(0xffffffffu, acc[q], off);
        }
        if (lane == 0) {
#pragma unroll
            for (int q = 0; q < QT; q++) s_sc[q][j] = acc[q];
        }
    }
    __syncthreads();

    // ---- Phase 2: masked softmax (store exp in s_sc, 1/sum in s_inv) ----
    const int vl = valid_lens[b];
    if (warp < QT) {
        const int q = warp;
        float mx = -3.4e38f;
        for (int j = lane; j < LK_; j += 32) {
            float s = (j < vl) ? s_sc[q][j] : NEG_FILL;
            mx = fmaxf(mx, s);
        }
#pragma unroll
        for (int off = 16; off; off >>= 1)
            mx = fmaxf(mx, __shfl_xor_sync(0xffffffffu, mx, off));
        float sum = 0.f;
        for (int j = lane; j < LK_; j += 32) {
            float s = (j < vl) ? s_sc[q][j] : NEG_FILL;
            float e = __expf(s - mx);
            s_sc[q][j] = e;
            sum += e;
        }
#pragma unroll
        for (int off = 16; off; off >>= 1)
            sum += __shfl_xor_sync(0xffffffffu, sum, off);
        if (lane == 0) s_inv[q] = 1.f / sum;
    }
    __syncthreads();

    // ---- Phase 3: out = (exp-weights @ values) * inv ----
    const float* vb = values + (size_t)b * LK_ * DV_;
    for (int t = tid; t < QT * (DV_ / 4); t += NTH) {
        const int q = t >> 7;        // DV_/4 = 128
        const int c = t & 127;
        float ax = 0.f, ay = 0.f, az = 0.f, aw = 0.f;
#pragma unroll 4
        for (int j = 0; j < LK_; j++) {
            const float a = s_sc[q][j];
            const float4 v = ((const float4*)(vb + (size_t)j * DV_))[c];
            ax += a * v.x; ay += a * v.y; az += a * v.z; aw += a * v.w;
        }
        const float inv = s_inv[q];
        float4 r = make_float4(ax * inv, ay * inv, az * inv, aw * inv);
        ((float4*)(out + (size_t)(b * LQ_ + q0 + q) * DV_))[c] = r;
    }
}

extern "C" void kernel_launch(void* const* d_in, const int* in_sizes, int n_in,
                              void* d_out, int out_size) {
    const float* queries = (const float*)d_in[0];
    const float* keys    = (const float*)d_in[1];
    const float* values  = (const float*)d_in[2];
    const float* Wq      = (const float*)d_in[3];
    const float* Wk      = (const float*)d_in[4];
    const float* wv      = (const float*)d_in[5];
    const int*   vlen    = (const int*)d_in[6];   // jax default demotes int64 -> int32
    float* out = (float*)d_out;

    dim3 blk(32, 32);
    proj_kernel<<<dim3(H_ / 32, (B_ * LQ_) / 32), blk>>>(queries, Wq, 0);
    proj_kernel<<<dim3(H_ / 32, (B_ * LK_) / 32), blk>>>(keys, Wk, 1);
    fused_attn<<<B_ * (LQ_ / QT), NTH>>>(values, wv, vlen, out);
}

// round 3
// speedup vs baseline: 3.0768x; 3.0768x over previous
#include <cuda_runtime.h>
#include <cuda_fp16.h>

// AdditiveAttention: out[b,i,:] = softmax_j( sum_h tanh(qp+kp)*wv, mask j<vl ) @ values
// B=8, LQ=128, LK=1024, D=512, H=256, DV=512

static constexpr int B_  = 8;
static constexpr int LQ_ = 128;
static constexpr int LK_ = 1024;
static constexpr int D_  = 512;
static constexpr int H_  = 256;
static constexpr int H2_ = 128;   // H/2 half2 pairs
static constexpr int DV_ = 512;
static constexpr int QT  = 8;
static constexpr int NTH = 512;

__device__ __half  g_qh[B_ * LQ_ * H_];       // q proj, [b*LQ+q][h] fp16
__device__ __half2 g_kT[B_ * H2_ * LK_];      // k proj, TRANSPOSED: [b][h2][j] half2

// ---------------- helpers ----------------
__device__ __forceinline__ unsigned cvt_tf32(float f) {
    unsigned r;
    asm("cvt.rna.tf32.f32 %0, %1;" : "=r"(r) : "f"(f));
    return r;
}

__device__ __forceinline__ void mma_tf32(float* c, const unsigned* a, const unsigned* b) {
    asm volatile(
        "mma.sync.aligned.m16n8k8.row.col.f32.tf32.tf32.f32 "
        "{%0,%1,%2,%3}, {%4,%5,%6,%7}, {%8,%9}, {%0,%1,%2,%3};"
        : "+f"(c[0]), "+f"(c[1]), "+f"(c[2]), "+f"(c[3])
        : "r"(a[0]), "r"(a[1]), "r"(a[2]), "r"(a[3]), "r"(b[0]), "r"(b[1]));
}

__device__ __forceinline__ __half2 htanh2(__half2 x) {
    unsigned xi = *reinterpret_cast<unsigned*>(&x), yi;
    asm("tanh.approx.f16x2 %0, %1;" : "=r"(yi) : "r"(xi));
    return *reinterpret_cast<__half2*>(&yi);
}

__device__ __forceinline__ float warp_sum(float v) {
#pragma unroll
    for (int off = 16; off; off >>= 1) v += __shfl_xor_sync(0xffffffffu, v, off);
    return v;
}
__device__ __forceinline__ float warp_max(float v) {
#pragma unroll
    for (int off = 16; off; off >>= 1) v = fmaxf(v, __shfl_xor_sync(0xffffffffu, v, off));
    return v;
}

// ---------------- projections: tf32 mma, tile 64x64, 128 threads ----------------
// which==0: C = g_qh row-major [row][h].  which==1: C = g_kT transposed [b][h2][j].
__global__ __launch_bounds__(128) void proj_mma(const float* __restrict__ A,
                                                const float* __restrict__ W,
                                                int which) {
    __shared__ float As[64][36];
    __shared__ float Ws[32][72];

    const int tid = threadIdx.x, warp = tid >> 5, lane = tid & 31;
    const int m0 = blockIdx.y * 64, n0 = blockIdx.x * 64;
    const int wm = (warp & 1) * 32, wn = (warp >> 1) * 32;
    const int g = lane >> 2, tg = lane & 3;

    float c[2][4][4];
#pragma unroll
    for (int mt = 0; mt < 2; mt++)
#pragma unroll
        for (int nt = 0; nt < 4; nt++)
#pragma unroll
            for (int i = 0; i < 4; i++) c[mt][nt][i] = 0.f;

    for (int k0 = 0; k0 < D_; k0 += 32) {
#pragma unroll
        for (int r = 0; r < 4; r++) {
            int row = (tid >> 3) + r * 16;
            float4 v = *(const float4*)&A[(size_t)(m0 + row) * D_ + k0 + (tid & 7) * 4];
            *(float4*)&As[row][(tid & 7) * 4] = v;
        }
#pragma unroll
        for (int r = 0; r < 4; r++) {
            int row = (tid >> 4) + r * 8;
            float4 v = *(const float4*)&W[(size_t)(k0 + row) * H_ + n0 + (tid & 15) * 4];
            *(float4*)&Ws[row][(tid & 15) * 4] = v;
        }
        __syncthreads();
#pragma unroll
        for (int ks = 0; ks < 4; ks++) {
            const int kb = ks * 8;
            unsigned a[2][4], b[4][2];
#pragma unroll
            for (int mt = 0; mt < 2; mt++) {
                int rb = wm + mt * 16 + g;
                a[mt][0] = cvt_tf32(As[rb][kb + tg]);
                a[mt][1] = cvt_tf32(As[rb + 8][kb + tg]);
                a[mt][2] = cvt_tf32(As[rb][kb + tg + 4]);
                a[mt][3] = cvt_tf32(As[rb + 8][kb + tg + 4]);
            }
#pragma unroll
            for (int nt = 0; nt < 4; nt++) {
                int cb = wn + nt * 8 + g;
                b[nt][0] = cvt_tf32(Ws[kb + tg][cb]);
                b[nt][1] = cvt_tf32(Ws[kb + tg + 4][cb]);
            }
#pragma unroll
            for (int mt = 0; mt < 2; mt++)
#pragma unroll
                for (int nt = 0; nt < 4; nt++) mma_tf32(c[mt][nt], a[mt], b[nt]);
        }
        __syncthreads();
    }

#pragma unroll
    for (int mt = 0; mt < 2; mt++)
#pragma unroll
        for (int nt = 0; nt < 4; nt++) {
            int row = m0 + wm + mt * 16 + g;               // global row
            int col = n0 + wn + nt * 8 + tg * 2;           // even col (pair base)
            __half2 lo = __floats2half2_rn(c[mt][nt][0], c[mt][nt][1]);
            __half2 hi = __floats2half2_rn(c[mt][nt][2], c[mt][nt][3]);
            if (which == 0) {
                *(__half2*)&g_qh[(size_t)row * H_ + col] = lo;
                *(__half2*)&g_qh[(size_t)(row + 8) * H_ + col] = hi;
            } else {
                int b_  = row >> 10, j = row & 1023;       // LK_=1024 rows per batch
                int h2  = col >> 1;
                g_kT[((size_t)b_ * H2_ + h2) * LK_ + j] = lo;
                g_kT[((size_t)b_ * H2_ + h2) * LK_ + (j + 8)] = hi;
            }
        }
}

// ---------------- fused attention ----------------
__global__ __launch_bounds__(NTH, 1) void fused_attn(
    const float* __restrict__ values,
    const float* __restrict__ wv,
    const int* __restrict__ valid_lens,
    float* __restrict__ out) {
    __shared__ float   s_sc[QT][LK_];    // scores -> exp weights (32 KB)
    __shared__ __half2 s_q[H2_][QT];     // q proj repacked [h2][q] (2 KB)
    __shared__ __half2 s_w[H2_];         // wv pairs (512 B)
    __shared__ float   s_inv[QT];

    const int b  = blockIdx.x >> 4;
    const int q0 = (blockIdx.x & 15) * QT;
    const int tid = threadIdx.x, warp = tid >> 5, lane = tid & 31;
    const int vl = valid_lens[b];

    // prologue: stage q rows + wv into smem
    if (tid < H2_) s_w[tid] = __floats2half2_rn(wv[2 * tid], wv[2 * tid + 1]);
    for (int i = tid; i < H2_ * QT; i += NTH) {
        int h2 = i >> 3, q = i & 7;
        s_q[h2][q] = ((const __half2*)g_qh)[(size_t)(b * LQ_ + q0 + q) * H2_ + h2];
    }
    __syncthreads();

    // ---- Phase 1: lane = key j, no cross-lane reduction ----
    for (int j0 = warp * 32; j0 < vl; j0 += NTH) {
        const int j = j0 + lane;                       // < LK_ always (safe load)
        const __half2* kcol = g_kT + (size_t)b * H2_ * LK_ + j;
        float accx[QT], accy[QT];
#pragma unroll
        for (int q = 0; q < QT; q++) { accx[q] = 0.f; accy[q] = 0.f; }

        for (int g4 = 0; g4 < H2_ / 4; g4++) {         // 32 groups of 4 h2
            __half2 acch[QT];
#pragma unroll
            for (int q = 0; q < QT; q++) acch[q] = __floats2half2_rn(0.f, 0.f);
#pragma unroll
            for (int hh = 0; hh < 4; hh++) {
                const int h2 = g4 * 4 + hh;
                const __half2 k2 = kcol[h2 * LK_];
                const __half2 w2 = s_w[h2];
                const uint4 qa = *(const uint4*)&s_q[h2][0];
                const uint4 qb = *(const uint4*)&s_q[h2][4];
                const __half2* qv0 = (const __half2*)&qa;
                const __half2* qv1 = (const __half2*)&qb;
#pragma unroll
                for (int q = 0; q < 4; q++)
                    acch[q] = __hfma2(htanh2(__hadd2(qv0[q], k2)), w2, acch[q]);
#pragma unroll
                for (int q = 0; q < 4; q++)
                    acch[4 + q] = __hfma2(htanh2(__hadd2(qv1[q], k2)), w2, acch[4 + q]);
            }
#pragma unroll
            for (int q = 0; q < QT; q++) {
                float2 f = __half22float2(acch[q]);
                accx[q] += f.x; accy[q] += f.y;
            }
        }
        if (j < vl) {
#pragma unroll
            for (int q = 0; q < QT; q++) s_sc[q][j] = accx[q] + accy[q];
        }
    }
    __syncthreads();

    // ---- Phase 2: masked softmax ----
    if (warp < QT) {
        const int q = warp;
        if (vl == 0) {
            for (int j = lane; j < LK_; j += 32) s_sc[q][j] = 1.0f;
            if (lane == 0) s_inv[q] = 1.0f / (float)LK_;
        } else {
            float mx = -3.4e38f;
            for (int j = lane; j < vl; j += 32) mx = fmaxf(mx, s_sc[q][j]);
            mx = warp_max(mx);
            float sum = 0.f;
            for (int j = lane; j < vl; j += 32) {
                float e = __expf(s_sc[q][j] - mx);
                s_sc[q][j] = e;
                sum += e;
            }
            sum = warp_sum(sum);
            if (lane == 0) s_inv[q] = 1.f / sum;
            const int jr = (vl + 3) & ~3;
            for (int j = vl + lane; j < jr; j += 32) s_sc[q][j] = 0.f;
        }
    }
    __syncthreads();

    // ---- Phase 3: out = (weights @ values) * inv, packed f32x2 FMA ----
    const int jmax = (vl == 0) ? LK_ : ((vl + 3) & ~3);
    if (warp < 8) {
        const int c = warp * 64 + lane * 2;            // warp owns 64 columns
        const float* vb = values + (size_t)b * LK_ * DV_;
        unsigned long long acc2[QT];
#pragma unroll
        for (int q = 0; q < QT; q++) acc2[q] = 0ull;

#pragma unroll 2
        for (int jg = 0; jg < jmax; jg += 4) {
            float4 s4[QT];
#pragma unroll
            for (int q = 0; q < QT; q++) s4[q] = *(const float4*)&s_sc[q][jg];
            unsigned long long v2r[4];
#pragma unroll
            for (int r = 0; r < 4; r++)
                v2r[r] = *(const unsigned long long*)&vb[(size_t)(jg + r) * DV_ + c];
#pragma unroll
            for (int r = 0; r < 4; r++) {
#pragma unroll
                for (int q = 0; q < QT; q++) {
                    float a = ((const float*)&s4[q])[r];
                    unsigned long long a2;
                    asm("mov.b64 %0, {%1, %1};" : "=l"(a2) : "f"(a));
                    asm("fma.rn.f32x2 %0, %1, %2, %0;"
                        : "+l"(acc2[q]) : "l"(a2), "l"(v2r[r]));
                }
            }
        }
#pragma unroll
        for (int q = 0; q < QT; q++) {
            float lo, hi;
            asm("mov.b64 {%0, %1}, %2;" : "=f"(lo), "=f"(hi) : "l"(acc2[q]));
            const float inv = s_inv[q];
            *(float2*)&out[(size_t)(b * LQ_ + q0 + q) * DV_ + c] =
                make_float2(lo * inv, hi * inv);
        }
    }
}

extern "C" void kernel_launch(void* const* d_in, const int* in_sizes, int n_in,
                              void* d_out, int out_size) {
    const float* queries = (const float*)d_in[0];
    const float* keys    = (const float*)d_in[1];
    const float* values  = (const float*)d_in[2];
    const float* Wq      = (const float*)d_in[3];
    const float* Wk      = (const float*)d_in[4];
    const float* wv      = (const float*)d_in[5];
    const int*   vlen    = (const int*)d_in[6];
    float* out = (float*)d_out;

    proj_mma<<<dim3(H_ / 64, (B_ * LQ_) / 64), 128>>>(queries, Wq, 0);
    proj_mma<<<dim3(H_ / 64, (B_ * LK_) / 64), 128>>>(keys, Wk, 1);
    fused_attn<<<B_ * (LQ_ / QT), NTH>>>(values, wv, vlen, out);
}

// round 4
// speedup vs baseline: 3.5441x; 1.1519x over previous
#include <cuda_runtime.h>
#include <cuda_fp16.h>

// AdditiveAttention: out[b,i,:] = softmax_j( sum_h tanh(qp+kp)*wv, mask j<vl ) @ values
// B=8, LQ=128, LK=1024, D=512, H=256, DV=512

static constexpr int B_  = 8;
static constexpr int LQ_ = 128;
static constexpr int LK_ = 1024;
static constexpr int D_  = 512;
static constexpr int H_  = 256;
static constexpr int H2_ = 128;
static constexpr int DV_ = 512;
static constexpr int QT  = 8;
static constexpr int NTH = 512;   // 16 warps: 8 producers + 8 consumers
static constexpr int TJ  = 256;   // key tile

__device__ __half  g_qh[B_ * LQ_ * H_];     // q proj [row][h] fp16
__device__ __half2 g_kT[B_ * H2_ * LK_];    // k proj transposed [b][h2][j]

// ---------------- helpers ----------------
__device__ __forceinline__ unsigned cvt_tf32(float f) {
    unsigned r;
    asm("cvt.rna.tf32.f32 %0, %1;" : "=r"(r) : "f"(f));
    return r;
}
__device__ __forceinline__ void mma_tf32(float* c, const unsigned* a, const unsigned* b) {
    asm volatile(
        "mma.sync.aligned.m16n8k8.row.col.f32.tf32.tf32.f32 "
        "{%0,%1,%2,%3}, {%4,%5,%6,%7}, {%8,%9}, {%0,%1,%2,%3};"
        : "+f"(c[0]), "+f"(c[1]), "+f"(c[2]), "+f"(c[3])
        : "r"(a[0]), "r"(a[1]), "r"(a[2]), "r"(a[3]), "r"(b[0]), "r"(b[1]));
}
__device__ __forceinline__ __half2 htanh2(__half2 x) {
    unsigned xi = *reinterpret_cast<unsigned*>(&x), yi;
    asm("tanh.approx.f16x2 %0, %1;" : "=r"(yi) : "r"(xi));
    return *reinterpret_cast<__half2*>(&yi);
}
__device__ __forceinline__ float warp_sum(float v) {
#pragma unroll
    for (int off = 16; off; off >>= 1) v += __shfl_xor_sync(0xffffffffu, v, off);
    return v;
}

// ---------------- fused projections: tf32 mma, tile 64x64, 128 threads ----------------
// blockIdx.y < 16  -> queries @ Wq -> g_qh (row-major)
// blockIdx.y >= 16 -> keys    @ Wk -> g_kT (transposed)
__global__ __launch_bounds__(128) void proj_mma(const float* __restrict__ Aq,
                                                const float* __restrict__ Ak,
                                                const float* __restrict__ Wq,
                                                const float* __restrict__ Wk) {
    __shared__ unsigned As[64][36];   // tf32 bits
    __shared__ unsigned Ws[32][72];

    const bool is_q = (blockIdx.y < 16);
    const float* A = is_q ? Aq : Ak;
    const float* W = is_q ? Wq : Wk;
    const int m0 = (is_q ? blockIdx.y : (blockIdx.y - 16)) * 64;
    const int n0 = blockIdx.x * 64;

    const int tid = threadIdx.x, warp = tid >> 5, lane = tid & 31;
    const int wm = (warp & 1) * 32, wn = (warp >> 1) * 32;
    const int g = lane >> 2, tg = lane & 3;

    float c[2][4][4];
#pragma unroll
    for (int mt = 0; mt < 2; mt++)
#pragma unroll
        for (int nt = 0; nt < 4; nt++)
#pragma unroll
            for (int i = 0; i < 4; i++) c[mt][nt][i] = 0.f;

    for (int k0 = 0; k0 < D_; k0 += 32) {
#pragma unroll
        for (int r = 0; r < 4; r++) {
            int row = (tid >> 3) + r * 16;
            float4 v = *(const float4*)&A[(size_t)(m0 + row) * D_ + k0 + (tid & 7) * 4];
            uint4 u = make_uint4(cvt_tf32(v.x), cvt_tf32(v.y), cvt_tf32(v.z), cvt_tf32(v.w));
            *(uint4*)&As[row][(tid & 7) * 4] = u;
        }
#pragma unroll
        for (int r = 0; r < 4; r++) {
            int row = (tid >> 4) + r * 8;
            float4 v = *(const float4*)&W[(size_t)(k0 + row) * H_ + n0 + (tid & 15) * 4];
            uint4 u = make_uint4(cvt_tf32(v.x), cvt_tf32(v.y), cvt_tf32(v.z), cvt_tf32(v.w));
            *(uint4*)&Ws[row][(tid & 15) * 4] = u;
        }
        __syncthreads();
#pragma unroll
        for (int ks = 0; ks < 4; ks++) {
            const int kb = ks * 8;
            unsigned a[2][4], b[4][2];
#pragma unroll
            for (int mt = 0; mt < 2; mt++) {
                int rb = wm + mt * 16 + g;
                a[mt][0] = As[rb][kb + tg];
                a[mt][1] = As[rb + 8][kb + tg];
                a[mt][2] = As[rb][kb + tg + 4];
                a[mt][3] = As[rb + 8][kb + tg + 4];
            }
#pragma unroll
            for (int nt = 0; nt < 4; nt++) {
                int cb = wn + nt * 8 + g;
                b[nt][0] = Ws[kb + tg][cb];
                b[nt][1] = Ws[kb + tg + 4][cb];
            }
#pragma unroll
            for (int mt = 0; mt < 2; mt++)
#pragma unroll
                for (int nt = 0; nt < 4; nt++) mma_tf32(c[mt][nt], a[mt], b[nt]);
        }
        __syncthreads();
    }

#pragma unroll
    for (int mt = 0; mt < 2; mt++)
#pragma unroll
        for (int nt = 0; nt < 4; nt++) {
            int row = m0 + wm + mt * 16 + g;
            int col = n0 + wn + nt * 8 + tg * 2;
            __half2 lo = __floats2half2_rn(c[mt][nt][0], c[mt][nt][1]);
            __half2 hi = __floats2half2_rn(c[mt][nt][2], c[mt][nt][3]);
            if (is_q) {
                *(__half2*)&g_qh[(size_t)row * H_ + col] = lo;
                *(__half2*)&g_qh[(size_t)(row + 8) * H_ + col] = hi;
            } else {
                int b_ = row >> 10, j = row & 1023;
                int h2 = col >> 1;
                g_kT[((size_t)b_ * H2_ + h2) * LK_ + j] = lo;
                g_kT[((size_t)b_ * H2_ + h2) * LK_ + (j + 8)] = hi;
            }
        }
}

// ---------------- fused attention: producer/consumer warp specialization ----------------
__global__ __launch_bounds__(NTH, 1) void fused_attn(
    const float* __restrict__ values,
    const float* __restrict__ wv,
    const int* __restrict__ valid_lens,
    float* __restrict__ out) {
    __shared__ float   s_e[2][TJ][QT];   // exp(score) tiles, [j][q] (16 KB)
    __shared__ __half2 s_q[H2_][QT];     // q proj [h2][q] (2 KB)
    __shared__ __half2 s_w[H2_];         // wv pairs
    __shared__ float   s_psum[8][QT];    // per-producer-warp partial sums

    const int b  = blockIdx.x >> 4;
    const int q0 = (blockIdx.x & 15) * QT;
    const int tid = threadIdx.x, warp = tid >> 5, lane = tid & 31;
    const int vl = valid_lens[b];
    const bool uniform = (vl == 0);
    const int T = uniform ? (LK_ / TJ) : ((vl + TJ - 1) / TJ);

    if (tid < H2_) s_w[tid] = __floats2half2_rn(wv[2 * tid], wv[2 * tid + 1]);
    for (int i = tid; i < H2_ * QT; i += NTH) {
        int h2 = i >> 3, q = i & 7;
        s_q[h2][q] = ((const __half2*)g_qh)[(size_t)(b * LQ_ + q0 + q) * H2_ + h2];
    }
    __syncthreads();

    if (warp < 8) {
        // ================= producers =================
        const int jl = warp * 32 + lane;                 // 0..255 within tile
        const __half2* kb0 = g_kT + (size_t)b * H2_ * LK_;
        float sum8[QT];
#pragma unroll
        for (int q = 0; q < QT; q++) sum8[q] = 0.f;

        auto produce = [&](int t) {
            const int j = t * TJ + jl;
            float e[QT];
            if (uniform) {
#pragma unroll
                for (int q = 0; q < QT; q++) e[q] = 1.0f;
            } else if (j < vl) {
                const __half2* kc = kb0 + j;
                float accx[QT], accy[QT];
#pragma unroll
                for (int q = 0; q < QT; q++) { accx[q] = 0.f; accy[q] = 0.f; }
                for (int g4 = 0; g4 < H2_ / 4; g4++) {
                    __half2 acch[QT];
#pragma unroll
                    for (int q = 0; q < QT; q++) acch[q] = __floats2half2_rn(0.f, 0.f);
#pragma unroll
                    for (int hh = 0; hh < 4; hh++) {
                        const int h2 = g4 * 4 + hh;
                        const __half2 k2 = kc[(size_t)h2 * LK_];
                        const __half2 w2 = s_w[h2];
                        const uint4 qa = *(const uint4*)&s_q[h2][0];
                        const uint4 qb = *(const uint4*)&s_q[h2][4];
                        const __half2* qv0 = (const __half2*)&qa;
                        const __half2* qv1 = (const __half2*)&qb;
#pragma unroll
                        for (int q = 0; q < 4; q++)
                            acch[q] = __hfma2(htanh2(__hadd2(qv0[q], k2)), w2, acch[q]);
#pragma unroll
                        for (int q = 0; q < 4; q++)
                            acch[4 + q] = __hfma2(htanh2(__hadd2(qv1[q], k2)), w2, acch[4 + q]);
                    }
#pragma unroll
                    for (int q = 0; q < QT; q++) {
                        float2 f = __half22float2(acch[q]);
                        accx[q] += f.x; accy[q] += f.y;
                    }
                }
#pragma unroll
                for (int q = 0; q < QT; q++) e[q] = __expf(accx[q] + accy[q]);
            } else {
#pragma unroll
                for (int q = 0; q < QT; q++) e[q] = 0.f;
            }
#pragma unroll
            for (int q = 0; q < QT; q++) sum8[q] += e[q];
            *(float4*)&s_e[t & 1][jl][0] = make_float4(e[0], e[1], e[2], e[3]);
            *(float4*)&s_e[t & 1][jl][4] = make_float4(e[4], e[5], e[6], e[7]);
        };

        produce(0);
        __syncthreads();
        for (int t = 0; t < T; t++) {
            if (t + 1 < T) {
                produce(t + 1);
            } else {
#pragma unroll
                for (int q = 0; q < QT; q++) {
                    float sq = warp_sum(sum8[q]);
                    if (lane == 0) s_psum[warp][q] = sq;
                }
            }
            __syncthreads();
        }
    } else {
        // ================= consumers =================
        const int c = (warp - 8) * 64 + lane * 2;        // warp owns 64 columns
        const float* vb = values + (size_t)b * LK_ * DV_;
        unsigned long long acc2[QT];
#pragma unroll
        for (int q = 0; q < QT; q++) acc2[q] = 0ull;

        __syncthreads();                                  // matches producers' post-produce(0)
        for (int t = 0; t < T; t++) {
            const int buf = t & 1;
            const float* vrow = vb + (size_t)t * TJ * DV_ + c;
#pragma unroll 4
            for (int jl = 0; jl < TJ; jl++) {
                const float4 elo = *(const float4*)&s_e[buf][jl][0];
                const float4 ehi = *(const float4*)&s_e[buf][jl][4];
                const unsigned long long v2 =
                    *(const unsigned long long*)(vrow + (size_t)jl * DV_);
                const float* ef0 = (const float*)&elo;
                const float* ef1 = (const float*)&ehi;
#pragma unroll
                for (int q = 0; q < 4; q++) {
                    unsigned long long a2;
                    asm("mov.b64 %0, {%1, %1};" : "=l"(a2) : "f"(ef0[q]));
                    asm("fma.rn.f32x2 %0, %1, %2, %0;" : "+l"(acc2[q]) : "l"(a2), "l"(v2));
                }
#pragma unroll
                for (int q = 0; q < 4; q++) {
                    unsigned long long a2;
                    asm("mov.b64 %0, {%1, %1};" : "=l"(a2) : "f"(ef1[q]));
                    asm("fma.rn.f32x2 %0, %1, %2, %0;" : "+l"(acc2[4 + q]) : "l"(a2), "l"(v2));
                }
            }
            __syncthreads();
        }

        // normalize + store
#pragma unroll
        for (int q = 0; q < QT; q++) {
            float sum = 0.f;
#pragma unroll
            for (int w = 0; w < 8; w++) sum += s_psum[w][q];
            const float inv = 1.f / sum;
            float lo, hi;
            asm("mov.b64 {%0, %1}, %2;" : "=f"(lo), "=f"(hi) : "l"(acc2[q]));
            *(float2*)&out[(size_t)(b * LQ_ + q0 + q) * DV_ + c] =
                make_float2(lo * inv, hi * inv);
        }
    }
}

extern "C" void kernel_launch(void* const* d_in, const int* in_sizes, int n_in,
                              void* d_out, int out_size) {
    const float* queries = (const float*)d_in[0];
    const float* keys    = (const float*)d_in[1];
    const float* values  = (const float*)d_in[2];
    const float* Wq      = (const float*)d_in[3];
    const float* Wk      = (const float*)d_in[4];
    const float* wv      = (const float*)d_in[5];
    const int*   vlen    = (const int*)d_in[6];
    float* out = (float*)d_out;

    proj_mma<<<dim3(H_ / 64, 16 + 128), 128>>>(queries, keys, Wq, Wk);
    fused_attn<<<B_ * (LQ_ / QT), NTH>>>(values, wv, vlen, out);
}